// round 10
// baseline (speedup 1.0000x reference)
#include <cuda_runtime.h>
#include <cstdint>

// Fixed shapes from reference setup_inputs
#define BS   32
#define C    256
#define HW   4096          // 64*64
#define HID  32            // C / R
#define NPLANES (BS * C)   // 8192

#define NCHUNK   2
#define B_PER_CH (BS / NCHUNK)              // 16 batches
#define P_PER_CH (B_PER_CH * C)             // 4096 planes = 67MB < 126MB L2

// Scratch in device globals (no allocations allowed)
__device__ float  g_pooled[NPLANES];   // [BS, C] plane means
__device__ float4 g_coef[NPLANES];     // (a0, a1, q0, q1) per (b,c)

// 128-bit write-through store: bypasses L2 allocation entirely, so the out
// stream CANNOT evict the L2-resident x chunk.
__device__ __forceinline__ void st_wt_v4(float4* p, float4 v) {
    asm volatile("st.global.wt.v4.f32 [%0], {%1, %2, %3, %4};"
                 :: "l"(p), "f"(v.x), "f"(v.y), "f"(v.z), "f"(v.w) : "memory");
}

// ---------------------------------------------------------------------------
// Kernel 1: mean pool for one chunk. One CTA per plane, 256 threads, 4
// front-batched float4 loads, default .ca so the 67MB chunk is L2-resident.
// ---------------------------------------------------------------------------
__global__ __launch_bounds__(256) void pool_kernel(const float* __restrict__ x,
                                                   int pbase) {
    const int p = pbase + blockIdx.x;
    const int t = threadIdx.x;
    const float4* __restrict__ x4 = reinterpret_cast<const float4*>(x) + (size_t)p * (HW / 4);

    float4 v0 = x4[t];
    float4 v1 = x4[t + 256];
    float4 v2 = x4[t + 512];
    float4 v3 = x4[t + 768];

    float s = ((v0.x + v0.y) + (v0.z + v0.w))
            + ((v1.x + v1.y) + (v1.z + v1.w))
            + ((v2.x + v2.y) + (v2.z + v2.w))
            + ((v3.x + v3.y) + (v3.z + v3.w));

#pragma unroll
    for (int o = 16; o > 0; o >>= 1) s += __shfl_down_sync(0xffffffffu, s, o);

    __shared__ float ws[8];
    if ((t & 31) == 0) ws[t >> 5] = s;
    __syncthreads();
    if (t < 8) {
        float v = ws[t];
#pragma unroll
        for (int o = 4; o > 0; o >>= 1) v += __shfl_down_sync(0xffu, v, o);
        if (t == 0) g_pooled[p] = v * (1.0f / (float)HW);
    }
}

// ---------------------------------------------------------------------------
// Kernel 2: coefficients for one chunk. One CTA per batch element.
// ---------------------------------------------------------------------------
__global__ __launch_bounds__(256) void coef_kernel(const float* __restrict__ w1,
                                                   const float* __restrict__ b1,
                                                   const float* __restrict__ w2,
                                                   const float* __restrict__ b2,
                                                   int bbase) {
    const int b = bbase + blockIdx.x;
    const int t = threadIdx.x;

    __shared__ float sp[C];
    __shared__ float sh[HID];

    sp[t] = g_pooled[b * C + t];
    __syncthreads();

    if (t < HID) {
        float acc = b1[t];
        const float* __restrict__ w1r = w1 + t * C;
#pragma unroll 8
        for (int i = 0; i < C; ++i) acc = fmaf(sp[i], w1r[i], acc);
        sh[t] = fmaxf(acc, 0.f);
    }
    __syncthreads();

    const int cc = t;
    float z00 = b2[2 * cc];               // k=0 alpha
    float z01 = b2[2 * cc + 1];           // k=0 beta
    float z10 = b2[512 + 2 * cc];         // k=1 alpha
    float z11 = b2[512 + 2 * cc + 1];     // k=1 beta
    const float* __restrict__ r00 = w2 + (size_t)(2 * cc) * HID;
    const float* __restrict__ r01 = w2 + (size_t)(2 * cc + 1) * HID;
    const float* __restrict__ r10 = w2 + (size_t)(512 + 2 * cc) * HID;
    const float* __restrict__ r11 = w2 + (size_t)(512 + 2 * cc + 1) * HID;
#pragma unroll
    for (int h = 0; h < HID; ++h) {
        const float hv = sh[h];
        z00 = fmaf(hv, r00[h], z00);
        z01 = fmaf(hv, r01[h], z01);
        z10 = fmaf(hv, r10[h], z10);
        z11 = fmaf(hv, r11[h], z11);
    }
    float4 cf;
    cf.x = 1.0f + tanhf(0.5f * z00);          // a0 = 1 + 1.0*delta
    cf.y =        tanhf(0.5f * z10);          // a1 = 0 + 1.0*delta
    cf.z = 1.0f + 0.5f * tanhf(0.5f * z01);   // q0 = 1 + 0.5*delta
    cf.w =        0.5f * tanhf(0.5f * z11);   // q1 = 0 + 0.5*delta
    g_coef[b * C + cc] = cf;
}

// ---------------------------------------------------------------------------
// Kernel 3: apply for one chunk: out = max(x*a0+q0, x*a1+q1).
// One plane per CTA (high-occupancy R2 geometry), REVERSE order within the
// chunk (consume the hottest tail of the chunk first), plain .ca reads
// (expected L2 hits), write-through stores (no L2 allocation for out).
// ---------------------------------------------------------------------------
__global__ __launch_bounds__(256) void apply_kernel(const float* __restrict__ x,
                                                    float* __restrict__ out,
                                                    int pbase) {
    const int p = pbase + (P_PER_CH - 1) - blockIdx.x;   // reverse in chunk
    const int t = threadIdx.x;

    const float4 cf = __ldcg(&g_coef[p]);
    const float a0 = cf.x, a1 = cf.y, q0 = cf.z, q1 = cf.w;

    const float4* __restrict__ x4 = reinterpret_cast<const float4*>(x) + (size_t)p * (HW / 4);
    float4* __restrict__ o4       = reinterpret_cast<float4*>(out)     + (size_t)p * (HW / 4);

    // Front-batched loads (MLP=4); default .ca — these should hit L2.
    float4 v0 = x4[t];
    float4 v1 = x4[t + 256];
    float4 v2 = x4[t + 512];
    float4 v3 = x4[t + 768];

    float4 r0, r1, r2, r3;
    r0.x = fmaxf(fmaf(v0.x, a0, q0), fmaf(v0.x, a1, q1));
    r0.y = fmaxf(fmaf(v0.y, a0, q0), fmaf(v0.y, a1, q1));
    r0.z = fmaxf(fmaf(v0.z, a0, q0), fmaf(v0.z, a1, q1));
    r0.w = fmaxf(fmaf(v0.w, a0, q0), fmaf(v0.w, a1, q1));
    r1.x = fmaxf(fmaf(v1.x, a0, q0), fmaf(v1.x, a1, q1));
    r1.y = fmaxf(fmaf(v1.y, a0, q0), fmaf(v1.y, a1, q1));
    r1.z = fmaxf(fmaf(v1.z, a0, q0), fmaf(v1.z, a1, q1));
    r1.w = fmaxf(fmaf(v1.w, a0, q0), fmaf(v1.w, a1, q1));
    r2.x = fmaxf(fmaf(v2.x, a0, q0), fmaf(v2.x, a1, q1));
    r2.y = fmaxf(fmaf(v2.y, a0, q0), fmaf(v2.y, a1, q1));
    r2.z = fmaxf(fmaf(v2.z, a0, q0), fmaf(v2.z, a1, q1));
    r2.w = fmaxf(fmaf(v2.w, a0, q0), fmaf(v2.w, a1, q1));
    r3.x = fmaxf(fmaf(v3.x, a0, q0), fmaf(v3.x, a1, q1));
    r3.y = fmaxf(fmaf(v3.y, a0, q0), fmaf(v3.y, a1, q1));
    r3.z = fmaxf(fmaf(v3.z, a0, q0), fmaf(v3.z, a1, q1));
    r3.w = fmaxf(fmaf(v3.w, a0, q0), fmaf(v3.w, a1, q1));

    st_wt_v4(&o4[t],       r0);
    st_wt_v4(&o4[t + 256], r1);
    st_wt_v4(&o4[t + 512], r2);
    st_wt_v4(&o4[t + 768], r3);
}

extern "C" void kernel_launch(void* const* d_in, const int* in_sizes, int n_in,
                              void* d_out, int out_size) {
    const float* x  = (const float*)d_in[0];
    const float* w1 = (const float*)d_in[1];
    const float* b1 = (const float*)d_in[2];
    const float* w2 = (const float*)d_in[3];
    const float* b2 = (const float*)d_in[4];
    float* out = (float*)d_out;

    for (int c = 0; c < NCHUNK; ++c) {
        const int pbase = c * P_PER_CH;
        const int bbase = c * B_PER_CH;
        pool_kernel <<<P_PER_CH, 256>>>(x, pbase);
        coef_kernel <<<B_PER_CH, 256>>>(w1, b1, w2, b2, bbase);
        apply_kernel<<<P_PER_CH, 256>>>(x, out, pbase);
    }
}

// round 12
// speedup vs baseline: 1.2752x; 1.2752x over previous
#include <cuda_runtime.h>
#include <cstdint>

// Fixed shapes from reference setup_inputs
#define BS   32
#define C    256
#define HW   4096          // 64*64
#define HID  32            // C / R
#define NPLANES (BS * C)   // 8192

// Planes [PIN_START, NPLANES) are pinned in L2 by pool (evict_last class):
// 6400 planes * 16KB = 100MB < 126MB L2, leaving slack for stores/metadata.
#define PIN_START 1792

// Scratch in device globals (no allocations allowed)
__device__ float  g_pooled[NPLANES];   // [BS, C] plane means
__device__ float4 g_coef[NPLANES];     // (a0, a1, q0, q1) per (b,c)

// --- 32-byte L2 eviction-priority loads (sm_103a requires >=256-bit form) ---
__device__ __forceinline__ void ld_evict_last_32B(const void* p, float4& a, float4& b) {
    unsigned long long r0, r1, r2, r3;
    asm volatile("ld.global.L2::evict_last.v4.b64 {%0,%1,%2,%3}, [%4];"
                 : "=l"(r0), "=l"(r1), "=l"(r2), "=l"(r3) : "l"(p));
    a.x = __uint_as_float((unsigned)r0);  a.y = __uint_as_float((unsigned)(r0 >> 32));
    a.z = __uint_as_float((unsigned)r1);  a.w = __uint_as_float((unsigned)(r1 >> 32));
    b.x = __uint_as_float((unsigned)r2);  b.y = __uint_as_float((unsigned)(r2 >> 32));
    b.z = __uint_as_float((unsigned)r3);  b.w = __uint_as_float((unsigned)(r3 >> 32));
}
__device__ __forceinline__ void ld_evict_first_32B(const void* p, float4& a, float4& b) {
    unsigned long long r0, r1, r2, r3;
    asm volatile("ld.global.L2::evict_first.v4.b64 {%0,%1,%2,%3}, [%4];"
                 : "=l"(r0), "=l"(r1), "=l"(r2), "=l"(r3) : "l"(p));
    a.x = __uint_as_float((unsigned)r0);  a.y = __uint_as_float((unsigned)(r0 >> 32));
    a.z = __uint_as_float((unsigned)r1);  a.w = __uint_as_float((unsigned)(r1 >> 32));
    b.x = __uint_as_float((unsigned)r2);  b.y = __uint_as_float((unsigned)(r2 >> 32));
    b.z = __uint_as_float((unsigned)r3);  b.w = __uint_as_float((unsigned)(r3 >> 32));
}

// ---------------------------------------------------------------------------
// Kernel 1: mean pool over H*W. One CTA per plane (proven geometry).
// Planes >= PIN_START: L2::evict_last (pinned for apply). Planes < PIN_START:
// L2::evict_first (never displace the pinned region).
// Each thread: 2 x 32B loads (64B total, same as before).
// ---------------------------------------------------------------------------
__global__ __launch_bounds__(256) void pool_kernel(const float* __restrict__ x) {
    const int p = blockIdx.x;                  // plane = b*C + c
    const int t = threadIdx.x;
    const char* base = reinterpret_cast<const char*>(x) + (size_t)p * (HW * 4);

    float4 v0, v1, v2, v3;
    if (p >= PIN_START) {
        ld_evict_last_32B(base + t * 32,        v0, v1);
        ld_evict_last_32B(base + 8192 + t * 32, v2, v3);
    } else {
        ld_evict_first_32B(base + t * 32,        v0, v1);
        ld_evict_first_32B(base + 8192 + t * 32, v2, v3);
    }

    float s = ((v0.x + v0.y) + (v0.z + v0.w))
            + ((v1.x + v1.y) + (v1.z + v1.w))
            + ((v2.x + v2.y) + (v2.z + v2.w))
            + ((v3.x + v3.y) + (v3.z + v3.w));

#pragma unroll
    for (int o = 16; o > 0; o >>= 1) s += __shfl_down_sync(0xffffffffu, s, o);

    __shared__ float ws[8];
    if ((t & 31) == 0) ws[t >> 5] = s;
    __syncthreads();
    if (t < 8) {
        float v = ws[t];
#pragma unroll
        for (int o = 4; o > 0; o >>= 1) v += __shfl_down_sync(0xffu, v, o);
        if (t == 0) g_pooled[p] = v * (1.0f / (float)HW);
    }
}

// ---------------------------------------------------------------------------
// Kernel 2: coefficients. One CTA per batch element (32 CTAs, 256 threads).
// ---------------------------------------------------------------------------
__global__ __launch_bounds__(256) void coef_kernel(const float* __restrict__ w1,
                                                   const float* __restrict__ b1,
                                                   const float* __restrict__ w2,
                                                   const float* __restrict__ b2) {
    const int b = blockIdx.x;
    const int t = threadIdx.x;

    __shared__ float sp[C];
    __shared__ float sh[HID];

    sp[t] = g_pooled[b * C + t];
    __syncthreads();

    if (t < HID) {
        float acc = b1[t];
        const float* __restrict__ w1r = w1 + t * C;
#pragma unroll 8
        for (int i = 0; i < C; ++i) acc = fmaf(sp[i], w1r[i], acc);
        sh[t] = fmaxf(acc, 0.f);
    }
    __syncthreads();

    const int cc = t;
    float z00 = b2[2 * cc];               // k=0 alpha
    float z01 = b2[2 * cc + 1];           // k=0 beta
    float z10 = b2[512 + 2 * cc];         // k=1 alpha
    float z11 = b2[512 + 2 * cc + 1];     // k=1 beta
    const float* __restrict__ r00 = w2 + (size_t)(2 * cc) * HID;
    const float* __restrict__ r01 = w2 + (size_t)(2 * cc + 1) * HID;
    const float* __restrict__ r10 = w2 + (size_t)(512 + 2 * cc) * HID;
    const float* __restrict__ r11 = w2 + (size_t)(512 + 2 * cc + 1) * HID;
#pragma unroll
    for (int h = 0; h < HID; ++h) {
        const float hv = sh[h];
        z00 = fmaf(hv, r00[h], z00);
        z01 = fmaf(hv, r01[h], z01);
        z10 = fmaf(hv, r10[h], z10);
        z11 = fmaf(hv, r11[h], z11);
    }
    float4 cf;
    cf.x = 1.0f + tanhf(0.5f * z00);          // a0 = 1 + 1.0*delta
    cf.y =        tanhf(0.5f * z10);          // a1 = 0 + 1.0*delta
    cf.z = 1.0f + 0.5f * tanhf(0.5f * z01);   // q0 = 1 + 0.5*delta
    cf.w =        0.5f * tanhf(0.5f * z11);   // q1 = 0 + 0.5*delta
    g_coef[b * C + cc] = cf;
}

// ---------------------------------------------------------------------------
// Kernel 3: out = max(x*a0+q0, x*a1+q1). One plane per CTA, REVERSE order:
// pinned planes [PIN_START, NPLANES) are consumed first as L2 hits.
// Reads: evict_first 32B loads (demote after single use, freeing pinned ways
// as the front advances). Stores: __stcs.
// ---------------------------------------------------------------------------
__global__ __launch_bounds__(256) void apply_kernel(const float* __restrict__ x,
                                                    float* __restrict__ out) {
    const int p = (NPLANES - 1) - blockIdx.x;   // reverse traversal
    const int t = threadIdx.x;

    const float4 cf = __ldcg(&g_coef[p]);
    const float a0 = cf.x, a1 = cf.y, q0 = cf.z, q1 = cf.w;

    const char* base = reinterpret_cast<const char*>(x) + (size_t)p * (HW * 4);
    float4* __restrict__ o4 = reinterpret_cast<float4*>(out) + (size_t)p * (HW / 4);

    float4 v0, v1, v2, v3;
    ld_evict_first_32B(base + t * 32,        v0, v1);
    ld_evict_first_32B(base + 8192 + t * 32, v2, v3);

#define APPLY4(r, v)                                                         \
    r.x = fmaxf(fmaf(v.x, a0, q0), fmaf(v.x, a1, q1));                       \
    r.y = fmaxf(fmaf(v.y, a0, q0), fmaf(v.y, a1, q1));                       \
    r.z = fmaxf(fmaf(v.z, a0, q0), fmaf(v.z, a1, q1));                       \
    r.w = fmaxf(fmaf(v.w, a0, q0), fmaf(v.w, a1, q1));

    float4 r0, r1, r2, r3;
    APPLY4(r0, v0) APPLY4(r1, v1) APPLY4(r2, v2) APPLY4(r3, v3)
#undef APPLY4

    // Store layout must mirror the 32B-load layout:
    // v0/v1 cover bytes [t*32, t*32+32), v2/v3 cover [8192 + t*32, ...+32).
    __stcs(&o4[2 * t],           r0);
    __stcs(&o4[2 * t + 1],       r1);
    __stcs(&o4[512 + 2 * t],     r2);
    __stcs(&o4[512 + 2 * t + 1], r3);
}

extern "C" void kernel_launch(void* const* d_in, const int* in_sizes, int n_in,
                              void* d_out, int out_size) {
    const float* x  = (const float*)d_in[0];
    const float* w1 = (const float*)d_in[1];
    const float* b1 = (const float*)d_in[2];
    const float* w2 = (const float*)d_in[3];
    const float* b2 = (const float*)d_in[4];
    float* out = (float*)d_out;

    pool_kernel <<<NPLANES, 256>>>(x);
    coef_kernel <<<BS,      256>>>(w1, b1, w2, b2);
    apply_kernel<<<NPLANES, 256>>>(x, out);
}

// round 13
// speedup vs baseline: 1.3545x; 1.0622x over previous
#include <cuda_runtime.h>
#include <cstdint>

// Fixed shapes from reference setup_inputs
#define BS   32
#define C    256
#define HW   4096          // 64*64
#define HID  32            // C / R
#define NPLANES (BS * C)   // 8192

// Scratch in device globals (no allocations allowed)
__device__ float  g_pooled[NPLANES];   // [BS, C] plane means
__device__ float4 g_coef[NPLANES];     // (a0, a1, q0, q1) per (b,c)

// ---------------------------------------------------------------------------
// Kernel 1: mean pool over H*W. One CTA per plane, 256 threads, 4 float4
// front-batched loads. (Proven 23.3us / 5.8TB/s geometry — unchanged.)
// ---------------------------------------------------------------------------
__global__ __launch_bounds__(256) void pool_kernel(const float* __restrict__ x) {
    const int p = blockIdx.x;                  // plane = b*C + c
    const int t = threadIdx.x;
    const float4* __restrict__ x4 = reinterpret_cast<const float4*>(x) + (size_t)p * (HW / 4);

    float4 v0 = x4[t];
    float4 v1 = x4[t + 256];
    float4 v2 = x4[t + 512];
    float4 v3 = x4[t + 768];

    float s = ((v0.x + v0.y) + (v0.z + v0.w))
            + ((v1.x + v1.y) + (v1.z + v1.w))
            + ((v2.x + v2.y) + (v2.z + v2.w))
            + ((v3.x + v3.y) + (v3.z + v3.w));

#pragma unroll
    for (int o = 16; o > 0; o >>= 1) s += __shfl_down_sync(0xffffffffu, s, o);

    __shared__ float ws[8];
    if ((t & 31) == 0) ws[t >> 5] = s;
    __syncthreads();
    if (t < 8) {
        float v = ws[t];
#pragma unroll
        for (int o = 4; o > 0; o >>= 1) v += __shfl_down_sync(0xffu, v, o);
        if (t == 0) g_pooled[p] = v * (1.0f / (float)HW);
    }
}

// ---------------------------------------------------------------------------
// Kernel 2: coefficients. One CTA per batch element (32 CTAs, 256 threads).
// ---------------------------------------------------------------------------
__global__ __launch_bounds__(256) void coef_kernel(const float* __restrict__ w1,
                                                   const float* __restrict__ b1,
                                                   const float* __restrict__ w2,
                                                   const float* __restrict__ b2) {
    const int b = blockIdx.x;
    const int t = threadIdx.x;

    __shared__ float sp[C];
    __shared__ float sh[HID];

    sp[t] = g_pooled[b * C + t];
    __syncthreads();

    if (t < HID) {
        float acc = b1[t];
        const float* __restrict__ w1r = w1 + t * C;
#pragma unroll 8
        for (int i = 0; i < C; ++i) acc = fmaf(sp[i], w1r[i], acc);
        sh[t] = fmaxf(acc, 0.f);
    }
    __syncthreads();

    const int cc = t;
    float z00 = b2[2 * cc];               // k=0 alpha
    float z01 = b2[2 * cc + 1];           // k=0 beta
    float z10 = b2[512 + 2 * cc];         // k=1 alpha
    float z11 = b2[512 + 2 * cc + 1];     // k=1 beta
    const float* __restrict__ r00 = w2 + (size_t)(2 * cc) * HID;
    const float* __restrict__ r01 = w2 + (size_t)(2 * cc + 1) * HID;
    const float* __restrict__ r10 = w2 + (size_t)(512 + 2 * cc) * HID;
    const float* __restrict__ r11 = w2 + (size_t)(512 + 2 * cc + 1) * HID;
#pragma unroll
    for (int h = 0; h < HID; ++h) {
        const float hv = sh[h];
        z00 = fmaf(hv, r00[h], z00);
        z01 = fmaf(hv, r01[h], z01);
        z10 = fmaf(hv, r10[h], z10);
        z11 = fmaf(hv, r11[h], z11);
    }
    float4 cf;
    cf.x = 1.0f + tanhf(0.5f * z00);          // a0 = 1 + 1.0*delta
    cf.y =        tanhf(0.5f * z10);          // a1 = 0 + 1.0*delta
    cf.z = 1.0f + 0.5f * tanhf(0.5f * z01);   // q0 = 1 + 0.5*delta
    cf.w =        0.5f * tanhf(0.5f * z11);   // q1 = 0 + 0.5*delta
    g_coef[b * C + cc] = cf;
}

// ---------------------------------------------------------------------------
// Kernel 3: out = max(x*a0+q0, x*a1+q1). One plane per CTA, block=128,
// 8 front-batched float4 loads per thread (MLP_p1=8) — deep L1tex queue at
// high CTA count. Forward order. __ldcs reads (single-use), __stcs stores.
// ---------------------------------------------------------------------------
__global__ __launch_bounds__(128) void apply_kernel(const float* __restrict__ x,
                                                    float* __restrict__ out) {
    const int p = blockIdx.x;                 // plane = b*C + c
    const int t = threadIdx.x;                // 0..127

    const float4 cf = __ldcg(&g_coef[p]);
    const float a0 = cf.x, a1 = cf.y, q0 = cf.z, q1 = cf.w;

    const float4* __restrict__ x4 = reinterpret_cast<const float4*>(x) + (size_t)p * (HW / 4);
    float4* __restrict__ o4       = reinterpret_cast<float4*>(out)     + (size_t)p * (HW / 4);

    // 8 front-batched 16B loads: thread t covers indices t + 128*i, i=0..7
    float4 v0 = __ldcs(&x4[t]);
    float4 v1 = __ldcs(&x4[t + 128]);
    float4 v2 = __ldcs(&x4[t + 256]);
    float4 v3 = __ldcs(&x4[t + 384]);
    float4 v4 = __ldcs(&x4[t + 512]);
    float4 v5 = __ldcs(&x4[t + 640]);
    float4 v6 = __ldcs(&x4[t + 768]);
    float4 v7 = __ldcs(&x4[t + 896]);

#define APPLY_ST(v, idx)                                                     \
    {                                                                        \
        float4 r;                                                            \
        r.x = fmaxf(fmaf(v.x, a0, q0), fmaf(v.x, a1, q1));                   \
        r.y = fmaxf(fmaf(v.y, a0, q0), fmaf(v.y, a1, q1));                   \
        r.z = fmaxf(fmaf(v.z, a0, q0), fmaf(v.z, a1, q1));                   \
        r.w = fmaxf(fmaf(v.w, a0, q0), fmaf(v.w, a1, q1));                   \
        __stcs(&o4[idx], r);                                                 \
    }

    APPLY_ST(v0, t)
    APPLY_ST(v1, t + 128)
    APPLY_ST(v2, t + 256)
    APPLY_ST(v3, t + 384)
    APPLY_ST(v4, t + 512)
    APPLY_ST(v5, t + 640)
    APPLY_ST(v6, t + 768)
    APPLY_ST(v7, t + 896)
#undef APPLY_ST
}

extern "C" void kernel_launch(void* const* d_in, const int* in_sizes, int n_in,
                              void* d_out, int out_size) {
    const float* x  = (const float*)d_in[0];
    const float* w1 = (const float*)d_in[1];
    const float* b1 = (const float*)d_in[2];
    const float* w2 = (const float*)d_in[3];
    const float* b2 = (const float*)d_in[4];
    float* out = (float*)d_out;

    pool_kernel <<<NPLANES, 256>>>(x);
    coef_kernel <<<BS,      256>>>(w1, b1, w2, b2);
    apply_kernel<<<NPLANES, 128>>>(x, out);
}

// round 14
// speedup vs baseline: 1.3753x; 1.0153x over previous
#include <cuda_runtime.h>
#include <cstdint>

// Fixed shapes from reference setup_inputs
#define BS   32
#define C    256
#define HW   4096          // 64*64
#define HID  32            // C / R
#define NPLANES (BS * C)   // 8192

// Scratch in device globals (no allocations allowed)
__device__ float  g_pooled[NPLANES];   // [BS, C] plane means
__device__ float4 g_coef[NPLANES];     // (a0, a1, q0, q1) per (b,c)

// ---------------------------------------------------------------------------
// Kernel 1: mean pool over H*W. One CTA per plane, 256 threads, 4 float4
// front-batched loads. (Proven 23.3us / 5.8TB/s geometry — unchanged.)
// ---------------------------------------------------------------------------
__global__ __launch_bounds__(256) void pool_kernel(const float* __restrict__ x) {
    const int p = blockIdx.x;                  // plane = b*C + c
    const int t = threadIdx.x;
    const float4* __restrict__ x4 = reinterpret_cast<const float4*>(x) + (size_t)p * (HW / 4);

    float4 v0 = x4[t];
    float4 v1 = x4[t + 256];
    float4 v2 = x4[t + 512];
    float4 v3 = x4[t + 768];

    float s = ((v0.x + v0.y) + (v0.z + v0.w))
            + ((v1.x + v1.y) + (v1.z + v1.w))
            + ((v2.x + v2.y) + (v2.z + v2.w))
            + ((v3.x + v3.y) + (v3.z + v3.w));

#pragma unroll
    for (int o = 16; o > 0; o >>= 1) s += __shfl_down_sync(0xffffffffu, s, o);

    __shared__ float ws[8];
    if ((t & 31) == 0) ws[t >> 5] = s;
    __syncthreads();
    if (t < 8) {
        float v = ws[t];
#pragma unroll
        for (int o = 4; o > 0; o >>= 1) v += __shfl_down_sync(0xffu, v, o);
        if (t == 0) g_pooled[p] = v * (1.0f / (float)HW);
    }
    // Allow the dependent coef grid to complete its prelaunch.
    cudaTriggerProgrammaticLaunchCompletion();
}

// ---------------------------------------------------------------------------
// Kernel 2: coefficients. One CTA per batch element (32 CTAs, 256 threads).
// PDL secondary: waits on pool completion before reading g_pooled.
// ---------------------------------------------------------------------------
__global__ __launch_bounds__(256) void coef_kernel(const float* __restrict__ w1,
                                                   const float* __restrict__ b1,
                                                   const float* __restrict__ w2,
                                                   const float* __restrict__ b2) {
    const int b = blockIdx.x;
    const int t = threadIdx.x;

    __shared__ float sp[C];
    __shared__ float sh[HID];

    // Wait for pool_kernel's g_pooled writes (PDL dependency barrier).
    cudaGridDependencySynchronize();

    sp[t] = g_pooled[b * C + t];
    __syncthreads();

    if (t < HID) {
        float acc = b1[t];
        const float* __restrict__ w1r = w1 + t * C;
#pragma unroll 8
        for (int i = 0; i < C; ++i) acc = fmaf(sp[i], w1r[i], acc);
        sh[t] = fmaxf(acc, 0.f);
    }
    __syncthreads();

    const int cc = t;
    float z00 = b2[2 * cc];               // k=0 alpha
    float z01 = b2[2 * cc + 1];           // k=0 beta
    float z10 = b2[512 + 2 * cc];         // k=1 alpha
    float z11 = b2[512 + 2 * cc + 1];     // k=1 beta
    const float* __restrict__ r00 = w2 + (size_t)(2 * cc) * HID;
    const float* __restrict__ r01 = w2 + (size_t)(2 * cc + 1) * HID;
    const float* __restrict__ r10 = w2 + (size_t)(512 + 2 * cc) * HID;
    const float* __restrict__ r11 = w2 + (size_t)(512 + 2 * cc + 1) * HID;
#pragma unroll
    for (int h = 0; h < HID; ++h) {
        const float hv = sh[h];
        z00 = fmaf(hv, r00[h], z00);
        z01 = fmaf(hv, r01[h], z01);
        z10 = fmaf(hv, r10[h], z10);
        z11 = fmaf(hv, r11[h], z11);
    }
    float4 cf;
    cf.x = 1.0f + tanhf(0.5f * z00);          // a0 = 1 + 1.0*delta
    cf.y =        tanhf(0.5f * z10);          // a1 = 0 + 1.0*delta
    cf.z = 1.0f + 0.5f * tanhf(0.5f * z01);   // q0 = 1 + 0.5*delta
    cf.w =        0.5f * tanhf(0.5f * z11);   // q1 = 0 + 0.5*delta
    g_coef[b * C + cc] = cf;

    cudaTriggerProgrammaticLaunchCompletion();
}

// ---------------------------------------------------------------------------
// Kernel 3: out = max(x*a0+q0, x*a1+q1). EXACT R2 geometry (best measured):
// one plane per CTA, 256 threads, 4 front-batched float4 loads, reverse
// order, __ldcs reads, __stcs stores. PDL secondary: waits before g_coef.
// ---------------------------------------------------------------------------
__global__ __launch_bounds__(256) void apply_kernel(const float* __restrict__ x,
                                                    float* __restrict__ out) {
    const int p = (NPLANES - 1) - blockIdx.x;   // reverse traversal
    const int t = threadIdx.x;

    // Wait for coef_kernel's g_coef writes (PDL dependency barrier).
    cudaGridDependencySynchronize();

    const float4 cf = __ldcg(&g_coef[p]);
    const float a0 = cf.x, a1 = cf.y, q0 = cf.z, q1 = cf.w;

    const float4* __restrict__ x4 = reinterpret_cast<const float4*>(x) + (size_t)p * (HW / 4);
    float4* __restrict__ o4       = reinterpret_cast<float4*>(out)     + (size_t)p * (HW / 4);

    float4 v0 = __ldcs(&x4[t]);
    float4 v1 = __ldcs(&x4[t + 256]);
    float4 v2 = __ldcs(&x4[t + 512]);
    float4 v3 = __ldcs(&x4[t + 768]);

    float4 r0, r1, r2, r3;
    r0.x = fmaxf(fmaf(v0.x, a0, q0), fmaf(v0.x, a1, q1));
    r0.y = fmaxf(fmaf(v0.y, a0, q0), fmaf(v0.y, a1, q1));
    r0.z = fmaxf(fmaf(v0.z, a0, q0), fmaf(v0.z, a1, q1));
    r0.w = fmaxf(fmaf(v0.w, a0, q0), fmaf(v0.w, a1, q1));
    r1.x = fmaxf(fmaf(v1.x, a0, q0), fmaf(v1.x, a1, q1));
    r1.y = fmaxf(fmaf(v1.y, a0, q0), fmaf(v1.y, a1, q1));
    r1.z = fmaxf(fmaf(v1.z, a0, q0), fmaf(v1.z, a1, q1));
    r1.w = fmaxf(fmaf(v1.w, a0, q0), fmaf(v1.w, a1, q1));
    r2.x = fmaxf(fmaf(v2.x, a0, q0), fmaf(v2.x, a1, q1));
    r2.y = fmaxf(fmaf(v2.y, a0, q0), fmaf(v2.y, a1, q1));
    r2.z = fmaxf(fmaf(v2.z, a0, q0), fmaf(v2.z, a1, q1));
    r2.w = fmaxf(fmaf(v2.w, a0, q0), fmaf(v2.w, a1, q1));
    r3.x = fmaxf(fmaf(v3.x, a0, q0), fmaf(v3.x, a1, q1));
    r3.y = fmaxf(fmaf(v3.y, a0, q0), fmaf(v3.y, a1, q1));
    r3.z = fmaxf(fmaf(v3.z, a0, q0), fmaf(v3.z, a1, q1));
    r3.w = fmaxf(fmaf(v3.w, a0, q0), fmaf(v3.w, a1, q1));

    __stcs(&o4[t],       r0);
    __stcs(&o4[t + 256], r1);
    __stcs(&o4[t + 512], r2);
    __stcs(&o4[t + 768], r3);
}

// Helper: launch with ProgrammaticStreamSerialization (PDL) attribute.
template <typename... Args>
static void launch_pdl(void (*kern)(Args...), dim3 grid, dim3 block, Args... args) {
    cudaLaunchAttribute attr[1];
    attr[0].id = cudaLaunchAttributeProgrammaticStreamSerialization;
    attr[0].val.programmaticStreamSerializationAllowed = 1;
    cudaLaunchConfig_t cfg = {};
    cfg.gridDim = grid;
    cfg.blockDim = block;
    cfg.dynamicSmemBytes = 0;
    cfg.stream = 0;
    cfg.attrs = attr;
    cfg.numAttrs = 1;
    cudaLaunchKernelEx(&cfg, kern, args...);
}

extern "C" void kernel_launch(void* const* d_in, const int* in_sizes, int n_in,
                              void* d_out, int out_size) {
    const float* x  = (const float*)d_in[0];
    const float* w1 = (const float*)d_in[1];
    const float* b1 = (const float*)d_in[2];
    const float* w2 = (const float*)d_in[3];
    const float* b2 = (const float*)d_in[4];
    float* out = (float*)d_out;

    pool_kernel<<<NPLANES, 256>>>(x);
    launch_pdl(coef_kernel, dim3(BS), dim3(256), w1, b1, w2, b2);
    launch_pdl(apply_kernel, dim3(NPLANES), dim3(256), x, out);
}